// round 14
// baseline (speedup 1.0000x reference)
#include <cuda_runtime.h>
#include <cuda_fp16.h>

#define EPSF 1e-6f
#define N_  4
#define L_  4096
#define H_  16
#define D_  64
#define NH  64
#define RS  1024            /* row stride in floats = H*D */
#define PER_N (L_*H_*D_)

// ---------------- scratch (device globals; no allocation allowed) ----------
__device__ float g_qsum_p [NH*16*64];
__device__ float g_ksum_p [NH*16*64];
__device__ float g_qnsum_p[NH*16*64];
__device__ float g_knsum_p[NH*16*64];
__device__ float g_crmax_p[NH*16];
__device__ float g_expsum_p[NH*16];
__device__ float g_nrow  [NH*L_];
__device__ float g_cr    [NH*L_];            // raw col_refine logits
__device__ float g_kv    [NH*D_*D_];         // zeroed in k3, atomically accumulated in k5
__device__ __align__(16) __half g_sq[(size_t)NH*L_*D_];
__device__ __align__(16) __half g_sk[(size_t)NH*L_*D_];

__device__ __forceinline__ float sigmoidf(float x) {
    float t;
    asm("tanh.approx.f32 %0, %1;" : "=f"(t) : "f"(0.5f * x));
    return fmaf(0.5f, t, 0.5f);
}
__device__ __forceinline__ int head_base(int nh) {
    int n = nh >> 4, h = nh & 15;
    return n * PER_N + h * D_;
}
__device__ __forceinline__ float2 h22f2(unsigned u) {
    return __half22float2(*reinterpret_cast<__half2*>(&u));
}
__device__ __forceinline__ void mma16816(float& c0, float& c1, float& c2, float& c3,
                                         unsigned a0, unsigned a1, unsigned a2, unsigned a3,
                                         unsigned b0, unsigned b1) {
    asm volatile(
        "mma.sync.aligned.m16n8k16.row.col.f32.f16.f16.f32 "
        "{%0,%1,%2,%3}, {%4,%5,%6,%7}, {%8,%9}, {%0,%1,%2,%3};"
        : "+f"(c0), "+f"(c1), "+f"(c2), "+f"(c3)
        : "r"(a0), "r"(a1), "r"(a2), "r"(a3), "r"(b0), "r"(b1));
}
__device__ __forceinline__ unsigned smem_u32(const void* p) {
    return (unsigned)__cvta_generic_to_shared(p);
}
__device__ __forceinline__ void ldsm_x4(unsigned& r0, unsigned& r1,
                                        unsigned& r2, unsigned& r3, unsigned a) {
    asm volatile("ldmatrix.sync.aligned.m8n8.x4.shared.b16 {%0,%1,%2,%3}, [%4];"
                 : "=r"(r0), "=r"(r1), "=r"(r2), "=r"(r3) : "r"(a));
}
__device__ __forceinline__ void ldsm_x4_t(unsigned& r0, unsigned& r1,
                                          unsigned& r2, unsigned& r3, unsigned a) {
    asm volatile("ldmatrix.sync.aligned.m8n8.x4.trans.shared.b16 {%0,%1,%2,%3}, [%4];"
                 : "=r"(r0), "=r"(r1), "=r"(r2), "=r"(r3) : "r"(a));
}

struct __align__(8) H4 { __half2 a, b; };

// ---------------- K1: sigmoid -> fp16 scratch + column-sum partials ---------
__global__ void __launch_bounds__(256) k1_sums(const float* __restrict__ Q,
                                               const float* __restrict__ K) {
    int nh = blockIdx.x, chunk = blockIdx.y;
    int t = threadIdx.x;
    int col = (t & 15) * 4;
    int rg  = t >> 4;
    const int base = head_base(nh);
    const size_t sbase = (size_t)nh * L_ * D_;
    float qs[4] = {}, ks[4] = {};
    int r0 = chunk * 256;
    #pragma unroll
    for (int ob = 0; ob < 4; ob++) {
        float4 q[4], k[4];
        #pragma unroll
        for (int i = 0; i < 4; i++) {
            int r = r0 + ob * 64 + i * 16 + rg;
            q[i] = *(const float4*)(Q + base + r * RS + col);
        }
        #pragma unroll
        for (int i = 0; i < 4; i++) {
            int r = r0 + ob * 64 + i * 16 + rg;
            k[i] = *(const float4*)(K + base + r * RS + col);
        }
        #pragma unroll
        for (int i = 0; i < 4; i++) {
            int r = r0 + ob * 64 + i * 16 + rg;
            float sq0 = sigmoidf(q[i].x), sq1 = sigmoidf(q[i].y);
            float sq2 = sigmoidf(q[i].z), sq3 = sigmoidf(q[i].w);
            float sk0 = sigmoidf(k[i].x), sk1 = sigmoidf(k[i].y);
            float sk2 = sigmoidf(k[i].z), sk3 = sigmoidf(k[i].w);
            qs[0] += sq0; qs[1] += sq1; qs[2] += sq2; qs[3] += sq3;
            ks[0] += sk0; ks[1] += sk1; ks[2] += sk2; ks[3] += sk3;
            H4 hq; hq.a = __floats2half2_rn(sq0, sq1); hq.b = __floats2half2_rn(sq2, sq3);
            H4 hk; hk.a = __floats2half2_rn(sk0, sk1); hk.b = __floats2half2_rn(sk2, sk3);
            size_t sidx = sbase + (size_t)r * D_ + col;
            *(H4*)(g_sq + sidx) = hq;
            *(H4*)(g_sk + sidx) = hk;
        }
    }
    __shared__ float qsum_s[64], ksum_s[64];
    if (t < 64) { qsum_s[t] = 0.f; ksum_s[t] = 0.f; }
    __syncthreads();
    #pragma unroll
    for (int i = 0; i < 4; i++) {
        atomicAdd(&qsum_s[col + i], qs[i]);
        atomicAdd(&ksum_s[col + i], ks[i]);
    }
    __syncthreads();
    if (t < 64) {
        g_qsum_p[(nh*16 + chunk)*64 + t] = qsum_s[t];
        g_ksum_p[(nh*16 + chunk)*64 + t] = ksum_s[t];
    }
}

// ---------------- K2: nrow + qn/kn partials, single pass, 8 thr/row ---------
__global__ void __launch_bounds__(256) k2_norm() {
    int nh = blockIdx.x, tile = blockIdx.y;    // 16 tiles x 256 rows
    int t = threadIdx.x;
    const size_t sbase = (size_t)nh * L_ * D_;
    int r0 = tile * 256;

    __shared__ float ksc[64], qsc[64];
    __shared__ float qn_pf[8][68], kn_pf[8][68];
    __shared__ float eps_q, eps_k;

    if (t < 64) {
        float a = 0.f, b = 0.f;
        #pragma unroll
        for (int c = 0; c < 16; c++) {
            a += g_ksum_p[(nh*16 + c)*64 + t];
            b += g_qsum_p[(nh*16 + c)*64 + t];
        }
        ksc[t] = a + EPSF;
        qsc[t] = b + EPSF;
    }
    __syncthreads();
    if (t == 0) {
        float a = 0.f, b = 0.f;
        #pragma unroll
        for (int c = 0; c < 64; c++) { a += ksc[c]; b += qsc[c]; }
        eps_q = EPSF * a;
        eps_k = EPSF * b;
    }
    __syncthreads();

    int sub = t & 7, grp = t >> 3;
    float ksr[8], qsr[8];
    #pragma unroll
    for (int j = 0; j < 8; j++) { ksr[j] = ksc[sub*8 + j]; qsr[j] = qsc[sub*8 + j]; }
    float epq = eps_q, epk = eps_k;

    const uint4* pq = (const uint4*)(g_sq + sbase);
    const uint4* pk = (const uint4*)(g_sk + sbase);
    float qn[8] = {}, kn[8] = {};

    #pragma unroll
    for (int pp = 0; pp < 4; pp++) {
        int rA = r0 + (pp*2)*32 + grp;
        int rB = rA + 32;
        uint4 uqA = pq[rA*8 + sub];
        uint4 ukA = pk[rA*8 + sub];
        uint4 uqB = pq[rB*8 + sub];
        uint4 ukB = pk[rB*8 + sub];
        #pragma unroll
        for (int half = 0; half < 2; half++) {
            uint4 uq = half ? uqB : uqA;
            uint4 uk = half ? ukB : ukA;
            int r = half ? rB : rA;
            unsigned wq[4] = {uq.x, uq.y, uq.z, uq.w};
            unsigned wk[4] = {uk.x, uk.y, uk.z, uk.w};
            float fq[8], fk[8];
            #pragma unroll
            for (int j = 0; j < 4; j++) {
                float2 a = h22f2(wq[j]); fq[2*j] = a.x; fq[2*j+1] = a.y;
                float2 b = h22f2(wk[j]); fk[2*j] = b.x; fk[2*j+1] = b.y;
            }
            float dq = 0.f, dk = 0.f;
            #pragma unroll
            for (int j = 0; j < 8; j++) { dq += fq[j]*ksr[j]; dk += fk[j]*qsr[j]; }
            #pragma unroll
            for (int o = 1; o < 8; o <<= 1) {
                dq += __shfl_xor_sync(0xffffffffu, dq, o);
                dk += __shfl_xor_sync(0xffffffffu, dk, o);
            }
            dq += epq; dk += epk;
            float nr = 1.0f / dq, nc = 1.0f / dk;
            if (sub == 0) g_nrow[nh*L_ + r] = nr;
            #pragma unroll
            for (int j = 0; j < 8; j++) { qn[j] += fq[j]*nr; kn[j] += fk[j]*nc; }
        }
    }
    #pragma unroll
    for (int o = 8; o <= 16; o <<= 1) {
        #pragma unroll
        for (int j = 0; j < 8; j++) {
            qn[j] += __shfl_xor_sync(0xffffffffu, qn[j], o);
            kn[j] += __shfl_xor_sync(0xffffffffu, kn[j], o);
        }
    }
    if ((t & 31) < 8) {
        int w = t >> 5;
        #pragma unroll
        for (int j = 0; j < 8; j++) {
            qn_pf[w][sub*8 + j] = qn[j];
            kn_pf[w][sub*8 + j] = kn[j];
        }
    }
    __syncthreads();
    if (t < 64) {
        float s = 0.f;
        #pragma unroll
        for (int w = 0; w < 8; w++) s += qn_pf[w][t];
        g_qnsum_p[(nh*16 + tile)*64 + t] = s;
    } else if (t < 128) {
        int c = t - 64;
        float s = 0.f;
        #pragma unroll
        for (int w = 0; w < 8; w++) s += kn_pf[w][c];
        g_knsum_p[(nh*16 + tile)*64 + c] = s;
    }
}

// ---------------- K3: cr + tile max/expsum (sk only) + zero kv slice --------
__global__ void __launch_bounds__(256) k3_refine() {
    int nh = blockIdx.x, tile = blockIdx.y;    // 16 tiles x 256 rows
    int t = threadIdx.x;
    const size_t sbase = (size_t)nh * L_ * D_;
    int r0 = tile * 256;

    __shared__ float qnc[64];
    __shared__ float eps_c;
    __shared__ float mx_s[8], es_s[8];
    __shared__ float bmax_sh;

    if (t < 64)
        *(float4*)&g_kv[nh*4096 + tile*256 + t*4] = make_float4(0.f, 0.f, 0.f, 0.f);

    if (t >= 64 && t < 128) {
        int c = t - 64;
        float b = 0.f;
        #pragma unroll
        for (int cc = 0; cc < 16; cc++) b += g_qnsum_p[(nh*16 + cc)*64 + c];
        qnc[c] = b + EPSF;
    }
    __syncthreads();
    if (t == 0) {
        float b = 0.f;
        #pragma unroll
        for (int c = 0; c < 64; c++) b += qnc[c];
        eps_c = EPSF * b;
    }
    __syncthreads();

    int sub = t & 7, grp = t >> 3;
    float qnr[8];
    #pragma unroll
    for (int j = 0; j < 8; j++) qnr[j] = qnc[sub*8 + j];
    float epc = eps_c;

    const uint4* pk = (const uint4*)(g_sk + sbase);
    uint4 rk[8];
    #pragma unroll
    for (int i = 0; i < 8; i++) rk[i] = pk[(r0 + i*32 + grp)*8 + sub];

    float mx = 0.f;     // cr strictly positive
    float dcv[8];
    #pragma unroll
    for (int i = 0; i < 8; i++) {
        int r = r0 + i*32 + grp;
        unsigned wk[4] = {rk[i].x, rk[i].y, rk[i].z, rk[i].w};
        float dc = 0.f;
        #pragma unroll
        for (int j = 0; j < 4; j++) {
            float2 b = h22f2(wk[j]);
            dc += b.x*qnr[2*j] + b.y*qnr[2*j+1];
        }
        #pragma unroll
        for (int o = 1; o < 8; o <<= 1)
            dc += __shfl_xor_sync(0xffffffffu, dc, o);
        dc += epc;
        dcv[i] = dc;
        if (sub == 0) g_cr[nh*L_ + r] = dc;
        mx = fmaxf(mx, dc);
    }
    #pragma unroll
    for (int o = 16; o; o >>= 1) mx = fmaxf(mx, __shfl_xor_sync(0xffffffffu, mx, o));
    if ((t & 31) == 0) mx_s[t >> 5] = mx;
    __syncthreads();
    if (t == 0) {
        float m = mx_s[0];
        #pragma unroll
        for (int i = 1; i < 8; i++) m = fmaxf(m, mx_s[i]);
        bmax_sh = m;
        g_crmax_p[nh*16 + tile] = m;
    }
    __syncthreads();
    {
        float bmax = bmax_sh;
        float es = 0.f;
        if (sub == 0) {
            #pragma unroll
            for (int j = 0; j < 8; j++) es += __expf(dcv[j] - bmax);
        }
        #pragma unroll
        for (int o = 16; o; o >>= 1) es += __shfl_xor_sync(0xffffffffu, es, o);
        if ((t & 31) == 0) es_s[t >> 5] = es;
        __syncthreads();
        if (t == 0) {
            float s = 0.f;
            #pragma unroll
            for (int i = 0; i < 8; i++) s += es_s[i];
            g_expsum_p[nh*16 + tile] = s;
        }
    }
}

// ---------------- K5: kv += (w*sk)^T @ V, 64-row tiles + HMMA ---------------
__global__ void __launch_bounds__(256) k5_kv(const float* __restrict__ V) {
    int nh = blockIdx.x, tile = blockIdx.y;    // 64 tiles x 64 rows
    int t = threadIdx.x;
    const int base = head_base(nh);
    const size_t sbase = (size_t)nh * L_ * D_;
    int s0g = tile * 64;

    __shared__ __align__(16) __half ksh[64*72];    // w*sk, s-major, pitch 72
    __shared__ __align__(16) __half vsh[64*72];    // V fp16 (unweighted), pitch 72
    __shared__ float wsh[64];

    // ---- front-issue ALL independent loads ----
    const uint4* skp = (const uint4*)(g_sk + sbase + (size_t)s0g * D_);
    uint4 skreg[2];
    #pragma unroll
    for (int p = 0; p < 2; p++) skreg[p] = skp[t + p*256];

    int l = t & 31;
    float crv = 0.f, pm = -1e30f, pe = 0.f;
    if (t < 64) {
        crv = g_cr[nh*L_ + s0g + t];
        if (l < 16) {
            pm = g_crmax_p[nh*16 + l];
            pe = g_expsum_p[nh*16 + l];
        }
    }

    // V fill — weight-independent, streams concurrently with the combine
    {
        int vrow = t >> 4, c4 = t & 15;
        #pragma unroll
        for (int p = 0; p < 4; p++) {
            int row = vrow + p*16;
            float4 f = *(const float4*)(V + base + (s0g + row)*RS + c4*4);
            __half2 h0 = __floats2half2_rn(f.x, f.y);
            __half2 h1 = __floats2half2_rn(f.z, f.w);
            uint2 u;
            u.x = *reinterpret_cast<unsigned*>(&h0);
            u.y = *reinterpret_cast<unsigned*>(&h1);
            *(uint2*)&vsh[row*72 + c4*4] = u;
        }
    }

    // per-warp redundant combine (warps 0-1), then weights
    if (t < 64) {
        float m = (l < 16) ? pm : -1e30f;
        #pragma unroll
        for (int o = 16; o; o >>= 1) m = fmaxf(m, __shfl_xor_sync(0xffffffffu, m, o));
        float e = (l < 16) ? __expf(pm - m) * pe : 0.f;
        #pragma unroll
        for (int o = 16; o; o >>= 1) e += __shfl_xor_sync(0xffffffffu, e, o);
        float scale = (float)L_ / e;
        wsh[t] = __expf(crv - m) * scale;
    }
    __syncthreads();

    // sk multiply by w (fp16) and store — short post-sync path
    #pragma unroll
    for (int p = 0; p < 2; p++) {
        int i = t + p*256;
        int row = i >> 3, j = i & 7;
        __half2 wv = __float2half2_rn(wsh[row]);
        uint4 u = skreg[p];
        __half2* h = (__half2*)&u;
        h[0] = __hmul2(h[0], wv); h[1] = __hmul2(h[1], wv);
        h[2] = __hmul2(h[2], wv); h[3] = __hmul2(h[3], wv);
        *(uint4*)&ksh[row*72 + j*8] = u;
    }
    __syncthreads();

    int w = t >> 5;
    int mt = w & 3, nhf = w >> 2;
    int m0 = mt * 16;
    int grow = l >> 2, kc = l & 3;
    float c[4][4] = {};

    int arow = (l & 7) + ((l >> 4) & 1) * 8;
    int acol = m0 + ((l >> 3) & 1) * 8;
    int brow = (l & 7) + ((l >> 3) & 1) * 8;
    int bcol = nhf*32 + (l >> 4) * 8;

    #pragma unroll
    for (int kt = 0; kt < 4; kt++) {
        unsigned a0, a1, a2, a3;
        ldsm_x4_t(a0, a1, a2, a3, smem_u32(&ksh[(kt*16 + arow)*72 + acol]));
        unsigned b0, b1, b2, b3, b4, b5, b6, b7;
        ldsm_x4_t(b0, b1, b2, b3, smem_u32(&vsh[(kt*16 + brow)*72 + bcol]));
        ldsm_x4_t(b4, b5, b6, b7, smem_u32(&vsh[(kt*16 + brow)*72 + bcol + 16]));
        mma16816(c[0][0], c[0][1], c[0][2], c[0][3], a0, a1, a2, a3, b0, b1);
        mma16816(c[1][0], c[1][1], c[1][2], c[1][3], a0, a1, a2, a3, b2, b3);
        mma16816(c[2][0], c[2][1], c[2][2], c[2][3], a0, a1, a2, a3, b4, b5);
        mma16816(c[3][0], c[3][1], c[3][2], c[3][3], a0, a1, a2, a3, b6, b7);
    }
    int drow = m0 + grow;
    #pragma unroll
    for (int nt = 0; nt < 4; nt++) {
        int e = nhf*32 + nt*8 + kc*2;
        float* dst = &g_kv[nh*4096 + drow*64 + e];
        atomicAdd(dst,     c[nt][0]);
        atomicAdd(dst + 1, c[nt][1]);
        atomicAdd(dst + 512,     c[nt][2]);
        atomicAdd(dst + 512 + 1, c[nt][3]);
    }
}

// ---------------- K6: out = (sq @ kv) * rowfac, HMMA + ldmatrix feeds -------
__global__ void __launch_bounds__(256) k6_out(float* __restrict__ O) {
    int nh = blockIdx.x, tile = blockIdx.y;    // 32 tiles x 128 rows
    int t = threadIdx.x;
    const int base = head_base(nh);
    const size_t sbase = (size_t)nh * L_ * D_;
    int r0g = tile * 128;

    __shared__ __align__(16) __half qsh[128*72];   // sq rows, pitch 72
    __shared__ __align__(16) __half kvsh[64*72];   // kv fp16, d-major, pitch 72
    __shared__ float rf[128];
    __shared__ float knc_s[64];

    float nrow_reg = 0.f;
    if (t < 128) nrow_reg = g_nrow[nh*L_ + r0g + t];
    if (t < 64) {
        float a = 0.f;
        #pragma unroll
        for (int cc = 0; cc < 16; cc++) a += g_knsum_p[(nh*16 + cc)*64 + t];
        knc_s[t] = a + EPSF;
    }
    // qsh fill (plain loads — overlap via scoreboard)
    {
        const uint4* p = (const uint4*)(g_sq + sbase + (size_t)r0g * D_);
        #pragma unroll
        for (int pass = 0; pass < 4; pass++) {
            int i = t + pass*256;
            uint4 u = p[i];
            int row = i >> 3, j = i & 7;
            *(uint4*)&qsh[row*72 + j*8] = u;
        }
    }
    // kvsh fill: 64 rows x 64 floats -> fp16
    {
        #pragma unroll
        for (int p = 0; p < 4; p++) {
            int i = t + p*256;
            int row = i >> 4, c4 = i & 15;
            float4 f = *(const float4*)&g_kv[nh*4096 + row*64 + c4*4];
            __half2 h0 = __floats2half2_rn(f.x, f.y);
            __half2 h1 = __floats2half2_rn(f.z, f.w);
            uint2 u;
            u.x = *reinterpret_cast<unsigned*>(&h0);
            u.y = *reinterpret_cast<unsigned*>(&h1);
            *(uint2*)&kvsh[row*72 + c4*4] = u;
        }
    }
    __syncthreads();

    // rowfac from staged sq: rf = nrow * sigmoid(sum(sq*knc) + eps*sum(knc))
    if (t < 128) {
        const unsigned* row = (const unsigned*)&qsh[t*72];
        float d = 0.f, se = 0.f;
        #pragma unroll
        for (int j = 0; j < 32; j++) {
            float2 f = h22f2(row[j]);
            float c0 = knc_s[2*j], c1 = knc_s[2*j+1];
            d += f.x*c0 + f.y*c1;
            se += c0 + c1;
        }
        rf[t] = nrow_reg * sigmoidf(fmaf(EPSF, se, d));
    }
    __syncthreads();

    int w = t >> 5, l = t & 31;
    int rb = w * 16;
    int grow = l >> 2, kc = l & 3;
    float c[8][4] = {};

    int arow = rb + (l & 7) + ((l >> 3) & 1) * 8;
    int acol = (l >> 4) * 8;
    int brow = (l & 7) + ((l >> 3) & 1) * 8;
    int bcol = (l >> 4) * 8;

    #pragma unroll
    for (int kt = 0; kt < 4; kt++) {
        unsigned a0, a1, a2, a3;
        ldsm_x4(a0, a1, a2, a3, smem_u32(&qsh[arow*72 + kt*16 + acol]));
        #pragma unroll
        for (int nb = 0; nb < 4; nb++) {
            unsigned b0, b1, b2, b3;
            ldsm_x4_t(b0, b1, b2, b3,
                      smem_u32(&kvsh[(kt*16 + brow)*72 + nb*16 + bcol]));
            mma16816(c[nb*2][0],   c[nb*2][1],   c[nb*2][2],   c[nb*2][3],
                     a0, a1, a2, a3, b0, b1);
            mma16816(c[nb*2+1][0], c[nb*2+1][1], c[nb*2+1][2], c[nb*2+1][3],
                     a0, a1, a2, a3, b2, b3);
        }
    }
    int rA = r0g + rb + grow;
    float f0 = rf[rb + grow], f1 = rf[rb + grow + 8];
    #pragma unroll
    for (int nt = 0; nt < 8; nt++) {
        int e = nt*8 + kc*2;
        float2 o0; o0.x = c[nt][0] * f0; o0.y = c[nt][1] * f0;
        float2 o1; o1.x = c[nt][2] * f1; o1.y = c[nt][3] * f1;
        *(float2*)(O + base + rA*RS + e)     = o0;
        *(float2*)(O + base + (rA+8)*RS + e) = o1;
    }
}

// ---------------- launch ----------------------------------------------------
extern "C" void kernel_launch(void* const* d_in, const int* in_sizes, int n_in,
                              void* d_out, int out_size) {
    const float* Q = (const float*)d_in[0];
    const float* K = (const float*)d_in[1];
    const float* V = (const float*)d_in[2];
    float* O = (float*)d_out;

    k1_sums   <<<dim3(NH, 16), 256>>>(Q, K);
    k2_norm   <<<dim3(NH, 16), 256>>>();
    k3_refine <<<dim3(NH, 16), 256>>>();
    k5_kv     <<<dim3(NH, 64), 256>>>(V);
    k6_out    <<<dim3(NH, 32), 256>>>(O);
}

// round 16
// speedup vs baseline: 1.1250x; 1.1250x over previous
#include <cuda_runtime.h>
#include <cuda_fp16.h>

#define EPSF 1e-6f
#define N_  4
#define L_  4096
#define H_  16
#define D_  64
#define NH  64
#define RS  1024            /* row stride in floats = H*D */
#define PER_N (L_*H_*D_)

// ---------------- scratch (device globals; no allocation allowed) ----------
__device__ float g_qsum_p [NH*16*64];
__device__ float g_ksum_p [NH*16*64];
__device__ float g_qnsum_p[NH*16*64];
__device__ float g_knsum_p[NH*16*64];
__device__ float g_crmax_p[NH*16];
__device__ float g_expsum_p[NH*16];
__device__ float g_nrow  [NH*L_];
__device__ float g_cr    [NH*L_];            // raw col_refine logits
__device__ float g_kv    [NH*D_*D_];         // zeroed in k3, atomically accumulated in k5
__device__ __align__(16) __half g_sq[(size_t)NH*L_*D_];
__device__ __align__(16) __half g_sk[(size_t)NH*L_*D_];

__device__ __forceinline__ float sigmoidf(float x) {
    float t;
    asm("tanh.approx.f32 %0, %1;" : "=f"(t) : "f"(0.5f * x));
    return fmaf(0.5f, t, 0.5f);
}
__device__ __forceinline__ int head_base(int nh) {
    int n = nh >> 4, h = nh & 15;
    return n * PER_N + h * D_;
}
__device__ __forceinline__ float2 h22f2(unsigned u) {
    return __half22float2(*reinterpret_cast<__half2*>(&u));
}
__device__ __forceinline__ void mma16816(float& c0, float& c1, float& c2, float& c3,
                                         unsigned a0, unsigned a1, unsigned a2, unsigned a3,
                                         unsigned b0, unsigned b1) {
    asm volatile(
        "mma.sync.aligned.m16n8k16.row.col.f32.f16.f16.f32 "
        "{%0,%1,%2,%3}, {%4,%5,%6,%7}, {%8,%9}, {%0,%1,%2,%3};"
        : "+f"(c0), "+f"(c1), "+f"(c2), "+f"(c3)
        : "r"(a0), "r"(a1), "r"(a2), "r"(a3), "r"(b0), "r"(b1));
}
__device__ __forceinline__ unsigned smem_u32(const void* p) {
    return (unsigned)__cvta_generic_to_shared(p);
}
__device__ __forceinline__ void ldsm_x4(unsigned& r0, unsigned& r1,
                                        unsigned& r2, unsigned& r3, unsigned a) {
    asm volatile("ldmatrix.sync.aligned.m8n8.x4.shared.b16 {%0,%1,%2,%3}, [%4];"
                 : "=r"(r0), "=r"(r1), "=r"(r2), "=r"(r3) : "r"(a));
}
__device__ __forceinline__ void ldsm_x4_t(unsigned& r0, unsigned& r1,
                                          unsigned& r2, unsigned& r3, unsigned a) {
    asm volatile("ldmatrix.sync.aligned.m8n8.x4.trans.shared.b16 {%0,%1,%2,%3}, [%4];"
                 : "=r"(r0), "=r"(r1), "=r"(r2), "=r"(r3) : "r"(a));
}
// streaming (evict-first policy) ops — legal at 128/64-bit widths
__device__ __forceinline__ float4 ldg_cs_f4(const float* p) {
    float4 v;
    asm volatile("ld.global.cs.v4.f32 {%0,%1,%2,%3}, [%4];"
                 : "=f"(v.x), "=f"(v.y), "=f"(v.z), "=f"(v.w) : "l"(p));
    return v;
}
__device__ __forceinline__ void stg_cs_f2(void* p, float2 v) {
    asm volatile("st.global.cs.v2.f32 [%0], {%1,%2};"
                 :: "l"(p), "f"(v.x), "f"(v.y) : "memory");
}

struct __align__(8) H4 { __half2 a, b; };

// ---------------- K1: sigmoid -> fp16 scratch + column-sum partials ---------
__global__ void __launch_bounds__(256) k1_sums(const float* __restrict__ Q,
                                               const float* __restrict__ K) {
    int nh = blockIdx.x, chunk = blockIdx.y;
    int t = threadIdx.x;
    int col = (t & 15) * 4;
    int rg  = t >> 4;
    const int base = head_base(nh);
    const size_t sbase = (size_t)nh * L_ * D_;
    float qs[4] = {}, ks[4] = {};
    int r0 = chunk * 256;
    #pragma unroll
    for (int ob = 0; ob < 4; ob++) {
        float4 q[4], k[4];
        #pragma unroll
        for (int i = 0; i < 4; i++) {
            int r = r0 + ob * 64 + i * 16 + rg;
            q[i] = ldg_cs_f4(Q + base + r * RS + col);
        }
        #pragma unroll
        for (int i = 0; i < 4; i++) {
            int r = r0 + ob * 64 + i * 16 + rg;
            k[i] = ldg_cs_f4(K + base + r * RS + col);
        }
        #pragma unroll
        for (int i = 0; i < 4; i++) {
            int r = r0 + ob * 64 + i * 16 + rg;
            float sq0 = sigmoidf(q[i].x), sq1 = sigmoidf(q[i].y);
            float sq2 = sigmoidf(q[i].z), sq3 = sigmoidf(q[i].w);
            float sk0 = sigmoidf(k[i].x), sk1 = sigmoidf(k[i].y);
            float sk2 = sigmoidf(k[i].z), sk3 = sigmoidf(k[i].w);
            qs[0] += sq0; qs[1] += sq1; qs[2] += sq2; qs[3] += sq3;
            ks[0] += sk0; ks[1] += sk1; ks[2] += sk2; ks[3] += sk3;
            H4 hq; hq.a = __floats2half2_rn(sq0, sq1); hq.b = __floats2half2_rn(sq2, sq3);
            H4 hk; hk.a = __floats2half2_rn(sk0, sk1); hk.b = __floats2half2_rn(sk2, sk3);
            size_t sidx = sbase + (size_t)r * D_ + col;
            *(H4*)(g_sq + sidx) = hq;
            *(H4*)(g_sk + sidx) = hk;
        }
    }
    __shared__ float qsum_s[64], ksum_s[64];
    if (t < 64) { qsum_s[t] = 0.f; ksum_s[t] = 0.f; }
    __syncthreads();
    #pragma unroll
    for (int i = 0; i < 4; i++) {
        atomicAdd(&qsum_s[col + i], qs[i]);
        atomicAdd(&ksum_s[col + i], ks[i]);
    }
    __syncthreads();
    if (t < 64) {
        g_qsum_p[(nh*16 + chunk)*64 + t] = qsum_s[t];
        g_ksum_p[(nh*16 + chunk)*64 + t] = ksum_s[t];
    }
}

// ---------------- K2: nrow + qn/kn partials, single pass, 8 thr/row ---------
__global__ void __launch_bounds__(256) k2_norm() {
    int nh = blockIdx.x, tile = blockIdx.y;    // 16 tiles x 256 rows
    int t = threadIdx.x;
    const size_t sbase = (size_t)nh * L_ * D_;
    int r0 = tile * 256;

    __shared__ float ksc[64], qsc[64];
    __shared__ float qn_pf[8][68], kn_pf[8][68];
    __shared__ float eps_q, eps_k;

    if (t < 64) {
        float a = 0.f, b = 0.f;
        #pragma unroll
        for (int c = 0; c < 16; c++) {
            a += g_ksum_p[(nh*16 + c)*64 + t];
            b += g_qsum_p[(nh*16 + c)*64 + t];
        }
        ksc[t] = a + EPSF;
        qsc[t] = b + EPSF;
    }
    __syncthreads();
    if (t == 0) {
        float a = 0.f, b = 0.f;
        #pragma unroll
        for (int c = 0; c < 64; c++) { a += ksc[c]; b += qsc[c]; }
        eps_q = EPSF * a;
        eps_k = EPSF * b;
    }
    __syncthreads();

    int sub = t & 7, grp = t >> 3;
    float ksr[8], qsr[8];
    #pragma unroll
    for (int j = 0; j < 8; j++) { ksr[j] = ksc[sub*8 + j]; qsr[j] = qsc[sub*8 + j]; }
    float epq = eps_q, epk = eps_k;

    const uint4* pq = (const uint4*)(g_sq + sbase);
    const uint4* pk = (const uint4*)(g_sk + sbase);
    float qn[8] = {}, kn[8] = {};

    #pragma unroll
    for (int pp = 0; pp < 4; pp++) {
        int rA = r0 + (pp*2)*32 + grp;
        int rB = rA + 32;
        uint4 uqA = pq[rA*8 + sub];
        uint4 ukA = pk[rA*8 + sub];
        uint4 uqB = pq[rB*8 + sub];
        uint4 ukB = pk[rB*8 + sub];
        #pragma unroll
        for (int half = 0; half < 2; half++) {
            uint4 uq = half ? uqB : uqA;
            uint4 uk = half ? ukB : ukA;
            int r = half ? rB : rA;
            unsigned wq[4] = {uq.x, uq.y, uq.z, uq.w};
            unsigned wk[4] = {uk.x, uk.y, uk.z, uk.w};
            float fq[8], fk[8];
            #pragma unroll
            for (int j = 0; j < 4; j++) {
                float2 a = h22f2(wq[j]); fq[2*j] = a.x; fq[2*j+1] = a.y;
                float2 b = h22f2(wk[j]); fk[2*j] = b.x; fk[2*j+1] = b.y;
            }
            float dq = 0.f, dk = 0.f;
            #pragma unroll
            for (int j = 0; j < 8; j++) { dq += fq[j]*ksr[j]; dk += fk[j]*qsr[j]; }
            #pragma unroll
            for (int o = 1; o < 8; o <<= 1) {
                dq += __shfl_xor_sync(0xffffffffu, dq, o);
                dk += __shfl_xor_sync(0xffffffffu, dk, o);
            }
            dq += epq; dk += epk;
            float nr = 1.0f / dq, nc = 1.0f / dk;
            if (sub == 0) g_nrow[nh*L_ + r] = nr;
            #pragma unroll
            for (int j = 0; j < 8; j++) { qn[j] += fq[j]*nr; kn[j] += fk[j]*nc; }
        }
    }
    #pragma unroll
    for (int o = 8; o <= 16; o <<= 1) {
        #pragma unroll
        for (int j = 0; j < 8; j++) {
            qn[j] += __shfl_xor_sync(0xffffffffu, qn[j], o);
            kn[j] += __shfl_xor_sync(0xffffffffu, kn[j], o);
        }
    }
    if ((t & 31) < 8) {
        int w = t >> 5;
        #pragma unroll
        for (int j = 0; j < 8; j++) {
            qn_pf[w][sub*8 + j] = qn[j];
            kn_pf[w][sub*8 + j] = kn[j];
        }
    }
    __syncthreads();
    if (t < 64) {
        float s = 0.f;
        #pragma unroll
        for (int w = 0; w < 8; w++) s += qn_pf[w][t];
        g_qnsum_p[(nh*16 + tile)*64 + t] = s;
    } else if (t < 128) {
        int c = t - 64;
        float s = 0.f;
        #pragma unroll
        for (int w = 0; w < 8; w++) s += kn_pf[w][c];
        g_knsum_p[(nh*16 + tile)*64 + c] = s;
    }
}

// ---------------- K3: cr + tile max/expsum (sk only) + zero kv slice --------
__global__ void __launch_bounds__(256) k3_refine() {
    int nh = blockIdx.x, tile = blockIdx.y;    // 16 tiles x 256 rows
    int t = threadIdx.x;
    const size_t sbase = (size_t)nh * L_ * D_;
    int r0 = tile * 256;

    __shared__ float qnc[64];
    __shared__ float eps_c;
    __shared__ float mx_s[8], es_s[8];
    __shared__ float bmax_sh;

    if (t < 64)
        *(float4*)&g_kv[nh*4096 + tile*256 + t*4] = make_float4(0.f, 0.f, 0.f, 0.f);

    if (t >= 64 && t < 128) {
        int c = t - 64;
        float b = 0.f;
        #pragma unroll
        for (int cc = 0; cc < 16; cc++) b += g_qnsum_p[(nh*16 + cc)*64 + c];
        qnc[c] = b + EPSF;
    }
    __syncthreads();
    if (t == 0) {
        float b = 0.f;
        #pragma unroll
        for (int c = 0; c < 64; c++) b += qnc[c];
        eps_c = EPSF * b;
    }
    __syncthreads();

    int sub = t & 7, grp = t >> 3;
    float qnr[8];
    #pragma unroll
    for (int j = 0; j < 8; j++) qnr[j] = qnc[sub*8 + j];
    float epc = eps_c;

    const uint4* pk = (const uint4*)(g_sk + sbase);
    uint4 rk[8];
    #pragma unroll
    for (int i = 0; i < 8; i++) rk[i] = pk[(r0 + i*32 + grp)*8 + sub];

    float mx = 0.f;     // cr strictly positive
    float dcv[8];
    #pragma unroll
    for (int i = 0; i < 8; i++) {
        int r = r0 + i*32 + grp;
        unsigned wk[4] = {rk[i].x, rk[i].y, rk[i].z, rk[i].w};
        float dc = 0.f;
        #pragma unroll
        for (int j = 0; j < 4; j++) {
            float2 b = h22f2(wk[j]);
            dc += b.x*qnr[2*j] + b.y*qnr[2*j+1];
        }
        #pragma unroll
        for (int o = 1; o < 8; o <<= 1)
            dc += __shfl_xor_sync(0xffffffffu, dc, o);
        dc += epc;
        dcv[i] = dc;
        if (sub == 0) g_cr[nh*L_ + r] = dc;
        mx = fmaxf(mx, dc);
    }
    #pragma unroll
    for (int o = 16; o; o >>= 1) mx = fmaxf(mx, __shfl_xor_sync(0xffffffffu, mx, o));
    if ((t & 31) == 0) mx_s[t >> 5] = mx;
    __syncthreads();
    if (t == 0) {
        float m = mx_s[0];
        #pragma unroll
        for (int i = 1; i < 8; i++) m = fmaxf(m, mx_s[i]);
        bmax_sh = m;
        g_crmax_p[nh*16 + tile] = m;
    }
    __syncthreads();
    {
        float bmax = bmax_sh;
        float es = 0.f;
        if (sub == 0) {
            #pragma unroll
            for (int j = 0; j < 8; j++) es += __expf(dcv[j] - bmax);
        }
        #pragma unroll
        for (int o = 16; o; o >>= 1) es += __shfl_xor_sync(0xffffffffu, es, o);
        if ((t & 31) == 0) es_s[t >> 5] = es;
        __syncthreads();
        if (t == 0) {
            float s = 0.f;
            #pragma unroll
            for (int i = 0; i < 8; i++) s += es_s[i];
            g_expsum_p[nh*16 + tile] = s;
        }
    }
}

// ---------------- K5: kv += (w*sk)^T @ V, de-serialized fills + HMMA --------
__global__ void __launch_bounds__(256, 4) k5_kv(const float* __restrict__ V) {
    int nh = blockIdx.x, tile = blockIdx.y;    // 32 tiles x 128 rows
    int t = threadIdx.x;
    const int base = head_base(nh);
    const size_t sbase = (size_t)nh * L_ * D_;
    int s0g = tile * 128;

    __shared__ __align__(16) __half ksh[128*72];   // w*sk, s-major, pitch 72
    __shared__ __align__(16) __half vsh[128*72];   // V fp16 (unweighted), pitch 72
    __shared__ float wsh[128];

    // ---- front-issue ALL independent loads ----
    const uint4* skp = (const uint4*)(g_sk + sbase + (size_t)s0g * D_);
    uint4 skreg[4];
    #pragma unroll
    for (int p = 0; p < 4; p++) skreg[p] = skp[t + p*256];

    int l = t & 31;
    float crv = 0.f, pm = -1e30f, pe = 0.f;
    if (t < 128) {
        crv = g_cr[nh*L_ + s0g + t];
        if (l < 16) {
            pm = g_crmax_p[nh*16 + l];
            pe = g_expsum_p[nh*16 + l];
        }
    }

    // V fill — weight-independent, streams concurrently with the combine
    {
        int vrow = t >> 4, c4 = t & 15;
        #pragma unroll
        for (int p = 0; p < 8; p++) {
            int row = vrow + p*16;
            float4 f = ldg_cs_f4(V + base + (s0g + row)*RS + c4*4);
            __half2 h0 = __floats2half2_rn(f.x, f.y);
            __half2 h1 = __floats2half2_rn(f.z, f.w);
            uint2 u;
            u.x = *reinterpret_cast<unsigned*>(&h0);
            u.y = *reinterpret_cast<unsigned*>(&h1);
            *(uint2*)&vsh[row*72 + c4*4] = u;
        }
    }

    // per-warp redundant combine (warps 0-3), then weights
    if (t < 128) {
        float m = (l < 16) ? pm : -1e30f;
        #pragma unroll
        for (int o = 16; o; o >>= 1) m = fmaxf(m, __shfl_xor_sync(0xffffffffu, m, o));
        float e = (l < 16) ? __expf(pm - m) * pe : 0.f;
        #pragma unroll
        for (int o = 16; o; o >>= 1) e += __shfl_xor_sync(0xffffffffu, e, o);
        float scale = (float)L_ / e;
        wsh[t] = __expf(crv - m) * scale;
    }
    __syncthreads();

    // sk multiply by w (fp16) and store — short post-sync path
    #pragma unroll
    for (int p = 0; p < 4; p++) {
        int i = t + p*256;
        int row = i >> 3, j = i & 7;
        __half2 wv = __float2half2_rn(wsh[row]);
        uint4 u = skreg[p];
        __half2* h = (__half2*)&u;
        h[0] = __hmul2(h[0], wv); h[1] = __hmul2(h[1], wv);
        h[2] = __hmul2(h[2], wv); h[3] = __hmul2(h[3], wv);
        *(uint4*)&ksh[row*72 + j*8] = u;
    }
    __syncthreads();

    int w = t >> 5;
    int mt = w & 3, nhf = w >> 2;
    int m0 = mt * 16;
    int grow = l >> 2, kc = l & 3;
    float c[4][4] = {};

    int arow = (l & 7) + ((l >> 4) & 1) * 8;
    int acol = m0 + ((l >> 3) & 1) * 8;
    int brow = (l & 7) + ((l >> 3) & 1) * 8;
    int bcol = nhf*32 + (l >> 4) * 8;

    #pragma unroll
    for (int kt = 0; kt < 8; kt++) {
        unsigned a0, a1, a2, a3;
        ldsm_x4_t(a0, a1, a2, a3, smem_u32(&ksh[(kt*16 + arow)*72 + acol]));
        unsigned b0, b1, b2, b3, b4, b5, b6, b7;
        ldsm_x4_t(b0, b1, b2, b3, smem_u32(&vsh[(kt*16 + brow)*72 + bcol]));
        ldsm_x4_t(b4, b5, b6, b7, smem_u32(&vsh[(kt*16 + brow)*72 + bcol + 16]));
        mma16816(c[0][0], c[0][1], c[0][2], c[0][3], a0, a1, a2, a3, b0, b1);
        mma16816(c[1][0], c[1][1], c[1][2], c[1][3], a0, a1, a2, a3, b2, b3);
        mma16816(c[2][0], c[2][1], c[2][2], c[2][3], a0, a1, a2, a3, b4, b5);
        mma16816(c[3][0], c[3][1], c[3][2], c[3][3], a0, a1, a2, a3, b6, b7);
    }
    int drow = m0 + grow;
    #pragma unroll
    for (int nt = 0; nt < 4; nt++) {
        int e = nhf*32 + nt*8 + kc*2;
        float* dst = &g_kv[nh*4096 + drow*64 + e];
        atomicAdd(dst,     c[nt][0]);
        atomicAdd(dst + 1, c[nt][1]);
        atomicAdd(dst + 512,     c[nt][2]);
        atomicAdd(dst + 512 + 1, c[nt][3]);
    }
}

// ---------------- K6: out = (sq @ kv) * rowfac, HMMA + ldmatrix feeds -------
__global__ void __launch_bounds__(256) k6_out(float* __restrict__ O) {
    int nh = blockIdx.x, tile = blockIdx.y;    // 32 tiles x 128 rows
    int t = threadIdx.x;
    const int base = head_base(nh);
    const size_t sbase = (size_t)nh * L_ * D_;
    int r0g = tile * 128;

    __shared__ __align__(16) __half qsh[128*72];   // sq rows, pitch 72
    __shared__ __align__(16) __half kvsh[64*72];   // kv fp16, d-major, pitch 72
    __shared__ float rf[128];
    __shared__ float knc_s[64];

    float nrow_reg = 0.f;
    if (t < 128) nrow_reg = g_nrow[nh*L_ + r0g + t];
    if (t < 64) {
        float a = 0.f;
        #pragma unroll
        for (int cc = 0; cc < 16; cc++) a += g_knsum_p[(nh*16 + cc)*64 + t];
        knc_s[t] = a + EPSF;
    }
    // qsh fill (plain loads — overlap via scoreboard)
    {
        const uint4* p = (const uint4*)(g_sq + sbase + (size_t)r0g * D_);
        #pragma unroll
        for (int pass = 0; pass < 4; pass++) {
            int i = t + pass*256;
            uint4 u = p[i];
            int row = i >> 3, j = i & 7;
            *(uint4*)&qsh[row*72 + j*8] = u;
        }
    }
    // kvsh fill: 64 rows x 64 floats -> fp16
    {
        #pragma unroll
        for (int p = 0; p < 4; p++) {
            int i = t + p*256;
            int row = i >> 4, c4 = i & 15;
            float4 f = *(const float4*)&g_kv[nh*4096 + row*64 + c4*4];
            __half2 h0 = __floats2half2_rn(f.x, f.y);
            __half2 h1 = __floats2half2_rn(f.z, f.w);
            uint2 u;
            u.x = *reinterpret_cast<unsigned*>(&h0);
            u.y = *reinterpret_cast<unsigned*>(&h1);
            *(uint2*)&kvsh[row*72 + c4*4] = u;
        }
    }
    __syncthreads();

    // rowfac from staged sq: rf = nrow * sigmoid(sum(sq*knc) + eps*sum(knc))
    if (t < 128) {
        const unsigned* row = (const unsigned*)&qsh[t*72];
        float d = 0.f, se = 0.f;
        #pragma unroll
        for (int j = 0; j < 32; j++) {
            float2 f = h22f2(row[j]);
            float c0 = knc_s[2*j], c1 = knc_s[2*j+1];
            d += f.x*c0 + f.y*c1;
            se += c0 + c1;
        }
        rf[t] = nrow_reg * sigmoidf(fmaf(EPSF, se, d));
    }
    __syncthreads();

    int w = t >> 5, l = t & 31;
    int rb = w * 16;
    int grow = l >> 2, kc = l & 3;
    float c[8][4] = {};

    int arow = rb + (l & 7) + ((l >> 3) & 1) * 8;
    int acol = (l >> 4) * 8;
    int brow = (l & 7) + ((l >> 3) & 1) * 8;
    int bcol = (l >> 4) * 8;

    #pragma unroll
    for (int kt = 0; kt < 4; kt++) {
        unsigned a0, a1, a2, a3;
        ldsm_x4(a0, a1, a2, a3, smem_u32(&qsh[arow*72 + kt*16 + acol]));
        #pragma unroll
        for (int nb = 0; nb < 4; nb++) {
            unsigned b0, b1, b2, b3;
            ldsm_x4_t(b0, b1, b2, b3,
                      smem_u32(&kvsh[(kt*16 + brow)*72 + nb*16 + bcol]));
            mma16816(c[nb*2][0],   c[nb*2][1],   c[nb*2][2],   c[nb*2][3],
                     a0, a1, a2, a3, b0, b1);
            mma16816(c[nb*2+1][0], c[nb*2+1][1], c[nb*2+1][2], c[nb*2+1][3],
                     a0, a1, a2, a3, b2, b3);
        }
    }
    int rA = r0g + rb + grow;
    float f0 = rf[rb + grow], f1 = rf[rb + grow + 8];
    #pragma unroll
    for (int nt = 0; nt < 8; nt++) {
        int e = nt*8 + kc*2;
        float2 o0; o0.x = c[nt][0] * f0; o0.y = c[nt][1] * f0;
        float2 o1; o1.x = c[nt][2] * f1; o1.y = c[nt][3] * f1;
        stg_cs_f2(O + base + rA*RS + e,     o0);
        stg_cs_f2(O + base + (rA+8)*RS + e, o1);
    }
}

// ---------------- launch ----------------------------------------------------
extern "C" void kernel_launch(void* const* d_in, const int* in_sizes, int n_in,
                              void* d_out, int out_size) {
    const float* Q = (const float*)d_in[0];
    const float* K = (const float*)d_in[1];
    const float* V = (const float*)d_in[2];
    float* O = (float*)d_out;

    k1_sums   <<<dim3(NH, 16), 256>>>(Q, K);
    k2_norm   <<<dim3(NH, 16), 256>>>();
    k3_refine <<<dim3(NH, 16), 256>>>();
    k5_kv     <<<dim3(NH, 32), 256>>>(V);
    k6_out    <<<dim3(NH, 32), 256>>>(O);
}

// round 17
// speedup vs baseline: 1.1438x; 1.0167x over previous
#include <cuda_runtime.h>
#include <cuda_fp16.h>

#define EPSF 1e-6f
#define N_  4
#define L_  4096
#define H_  16
#define D_  64
#define NH  64
#define RS  1024            /* row stride in floats = H*D */
#define PER_N (L_*H_*D_)

// ---------------- scratch (device globals; no allocation allowed) ----------
__device__ float g_qsum_p [NH*16*64];
__device__ float g_ksum_p [NH*16*64];
__device__ float g_qnsum_p[NH*16*64];
__device__ float g_knsum_p[NH*16*64];
__device__ float g_crmax_p[NH*16];
__device__ float g_expsum_p[NH*16];
__device__ float g_nrow  [NH*L_];
__device__ float g_cr    [NH*L_];            // raw col_refine logits
__device__ float g_kv    [NH*D_*D_];         // zeroed in k3, reduced into by k5
__device__ __align__(16) __half g_sq[(size_t)NH*L_*D_];
__device__ __align__(16) __half g_sk[(size_t)NH*L_*D_];

__device__ __forceinline__ float sigmoidf(float x) {
    float t;
    asm("tanh.approx.f32 %0, %1;" : "=f"(t) : "f"(0.5f * x));
    return fmaf(0.5f, t, 0.5f);
}
__device__ __forceinline__ int head_base(int nh) {
    int n = nh >> 4, h = nh & 15;
    return n * PER_N + h * D_;
}
__device__ __forceinline__ float2 h22f2(unsigned u) {
    return __half22float2(*reinterpret_cast<__half2*>(&u));
}
__device__ __forceinline__ void mma16816(float& c0, float& c1, float& c2, float& c3,
                                         unsigned a0, unsigned a1, unsigned a2, unsigned a3,
                                         unsigned b0, unsigned b1) {
    asm volatile(
        "mma.sync.aligned.m16n8k16.row.col.f32.f16.f16.f32 "
        "{%0,%1,%2,%3}, {%4,%5,%6,%7}, {%8,%9}, {%0,%1,%2,%3};"
        : "+f"(c0), "+f"(c1), "+f"(c2), "+f"(c3)
        : "r"(a0), "r"(a1), "r"(a2), "r"(a3), "r"(b0), "r"(b1));
}
__device__ __forceinline__ unsigned smem_u32(const void* p) {
    return (unsigned)__cvta_generic_to_shared(p);
}
__device__ __forceinline__ void ldsm_x4(unsigned& r0, unsigned& r1,
                                        unsigned& r2, unsigned& r3, unsigned a) {
    asm volatile("ldmatrix.sync.aligned.m8n8.x4.shared.b16 {%0,%1,%2,%3}, [%4];"
                 : "=r"(r0), "=r"(r1), "=r"(r2), "=r"(r3) : "r"(a));
}
__device__ __forceinline__ void ldsm_x4_t(unsigned& r0, unsigned& r1,
                                          unsigned& r2, unsigned& r3, unsigned a) {
    asm volatile("ldmatrix.sync.aligned.m8n8.x4.trans.shared.b16 {%0,%1,%2,%3}, [%4];"
                 : "=r"(r0), "=r"(r1), "=r"(r2), "=r"(r3) : "r"(a));
}
// streaming (evict-first policy) ops — legal at 128/64-bit widths
__device__ __forceinline__ float4 ldg_cs_f4(const float* p) {
    float4 v;
    asm volatile("ld.global.cs.v4.f32 {%0,%1,%2,%3}, [%4];"
                 : "=f"(v.x), "=f"(v.y), "=f"(v.z), "=f"(v.w) : "l"(p));
    return v;
}
__device__ __forceinline__ void stg_cs_f2(void* p, float2 v) {
    asm volatile("st.global.cs.v2.f32 [%0], {%1,%2};"
                 :: "l"(p), "f"(v.x), "f"(v.y) : "memory");
}
// vector reduction (sm_90+): one LTS op for two adjacent floats
__device__ __forceinline__ void red_add_v2(float* p, float a, float b) {
    asm volatile("red.global.add.v2.f32 [%0], {%1,%2};"
                 :: "l"(p), "f"(a), "f"(b) : "memory");
}

struct __align__(8) H4 { __half2 a, b; };

// ---------------- K1: sigmoid -> fp16 scratch + column-sum partials ---------
__global__ void __launch_bounds__(256) k1_sums(const float* __restrict__ Q,
                                               const float* __restrict__ K) {
    int nh = blockIdx.x, chunk = blockIdx.y;
    int t = threadIdx.x;
    int col = (t & 15) * 4;
    int rg  = t >> 4;
    const int base = head_base(nh);
    const size_t sbase = (size_t)nh * L_ * D_;
    float qs[4] = {}, ks[4] = {};
    int r0 = chunk * 256;
    #pragma unroll
    for (int ob = 0; ob < 4; ob++) {
        float4 q[4], k[4];
        #pragma unroll
        for (int i = 0; i < 4; i++) {
            int r = r0 + ob * 64 + i * 16 + rg;
            q[i] = ldg_cs_f4(Q + base + r * RS + col);
        }
        #pragma unroll
        for (int i = 0; i < 4; i++) {
            int r = r0 + ob * 64 + i * 16 + rg;
            k[i] = ldg_cs_f4(K + base + r * RS + col);
        }
        #pragma unroll
        for (int i = 0; i < 4; i++) {
            int r = r0 + ob * 64 + i * 16 + rg;
            float sq0 = sigmoidf(q[i].x), sq1 = sigmoidf(q[i].y);
            float sq2 = sigmoidf(q[i].z), sq3 = sigmoidf(q[i].w);
            float sk0 = sigmoidf(k[i].x), sk1 = sigmoidf(k[i].y);
            float sk2 = sigmoidf(k[i].z), sk3 = sigmoidf(k[i].w);
            qs[0] += sq0; qs[1] += sq1; qs[2] += sq2; qs[3] += sq3;
            ks[0] += sk0; ks[1] += sk1; ks[2] += sk2; ks[3] += sk3;
            H4 hq; hq.a = __floats2half2_rn(sq0, sq1); hq.b = __floats2half2_rn(sq2, sq3);
            H4 hk; hk.a = __floats2half2_rn(sk0, sk1); hk.b = __floats2half2_rn(sk2, sk3);
            size_t sidx = sbase + (size_t)r * D_ + col;
            *(H4*)(g_sq + sidx) = hq;
            *(H4*)(g_sk + sidx) = hk;
        }
    }
    __shared__ float qsum_s[64], ksum_s[64];
    if (t < 64) { qsum_s[t] = 0.f; ksum_s[t] = 0.f; }
    __syncthreads();
    #pragma unroll
    for (int i = 0; i < 4; i++) {
        atomicAdd(&qsum_s[col + i], qs[i]);
        atomicAdd(&ksum_s[col + i], ks[i]);
    }
    __syncthreads();
    if (t < 64) {
        g_qsum_p[(nh*16 + chunk)*64 + t] = qsum_s[t];
        g_ksum_p[(nh*16 + chunk)*64 + t] = ksum_s[t];
    }
}

// ---------------- K2: nrow + qn/kn partials, single pass, 8 thr/row ---------
__global__ void __launch_bounds__(256) k2_norm() {
    int nh = blockIdx.x, tile = blockIdx.y;    // 16 tiles x 256 rows
    int t = threadIdx.x;
    const size_t sbase = (size_t)nh * L_ * D_;
    int r0 = tile * 256;

    __shared__ float ksc[64], qsc[64];
    __shared__ float qn_pf[8][68], kn_pf[8][68];
    __shared__ float eps_q, eps_k;

    if (t < 64) {
        float a = 0.f, b = 0.f;
        #pragma unroll
        for (int c = 0; c < 16; c++) {
            a += g_ksum_p[(nh*16 + c)*64 + t];
            b += g_qsum_p[(nh*16 + c)*64 + t];
        }
        ksc[t] = a + EPSF;
        qsc[t] = b + EPSF;
    }
    __syncthreads();
    if (t == 0) {
        float a = 0.f, b = 0.f;
        #pragma unroll
        for (int c = 0; c < 64; c++) { a += ksc[c]; b += qsc[c]; }
        eps_q = EPSF * a;
        eps_k = EPSF * b;
    }
    __syncthreads();

    int sub = t & 7, grp = t >> 3;
    float ksr[8], qsr[8];
    #pragma unroll
    for (int j = 0; j < 8; j++) { ksr[j] = ksc[sub*8 + j]; qsr[j] = qsc[sub*8 + j]; }
    float epq = eps_q, epk = eps_k;

    const uint4* pq = (const uint4*)(g_sq + sbase);
    const uint4* pk = (const uint4*)(g_sk + sbase);
    float qn[8] = {}, kn[8] = {};

    #pragma unroll
    for (int pp = 0; pp < 4; pp++) {
        int rA = r0 + (pp*2)*32 + grp;
        int rB = rA + 32;
        uint4 uqA = pq[rA*8 + sub];
        uint4 ukA = pk[rA*8 + sub];
        uint4 uqB = pq[rB*8 + sub];
        uint4 ukB = pk[rB*8 + sub];
        #pragma unroll
        for (int half = 0; half < 2; half++) {
            uint4 uq = half ? uqB : uqA;
            uint4 uk = half ? ukB : ukA;
            int r = half ? rB : rA;
            unsigned wq[4] = {uq.x, uq.y, uq.z, uq.w};
            unsigned wk[4] = {uk.x, uk.y, uk.z, uk.w};
            float fq[8], fk[8];
            #pragma unroll
            for (int j = 0; j < 4; j++) {
                float2 a = h22f2(wq[j]); fq[2*j] = a.x; fq[2*j+1] = a.y;
                float2 b = h22f2(wk[j]); fk[2*j] = b.x; fk[2*j+1] = b.y;
            }
            float dq = 0.f, dk = 0.f;
            #pragma unroll
            for (int j = 0; j < 8; j++) { dq += fq[j]*ksr[j]; dk += fk[j]*qsr[j]; }
            #pragma unroll
            for (int o = 1; o < 8; o <<= 1) {
                dq += __shfl_xor_sync(0xffffffffu, dq, o);
                dk += __shfl_xor_sync(0xffffffffu, dk, o);
            }
            dq += epq; dk += epk;
            float nr = 1.0f / dq, nc = 1.0f / dk;
            if (sub == 0) g_nrow[nh*L_ + r] = nr;
            #pragma unroll
            for (int j = 0; j < 8; j++) { qn[j] += fq[j]*nr; kn[j] += fk[j]*nc; }
        }
    }
    #pragma unroll
    for (int o = 8; o <= 16; o <<= 1) {
        #pragma unroll
        for (int j = 0; j < 8; j++) {
            qn[j] += __shfl_xor_sync(0xffffffffu, qn[j], o);
            kn[j] += __shfl_xor_sync(0xffffffffu, kn[j], o);
        }
    }
    if ((t & 31) < 8) {
        int w = t >> 5;
        #pragma unroll
        for (int j = 0; j < 8; j++) {
            qn_pf[w][sub*8 + j] = qn[j];
            kn_pf[w][sub*8 + j] = kn[j];
        }
    }
    __syncthreads();
    if (t < 64) {
        float s = 0.f;
        #pragma unroll
        for (int w = 0; w < 8; w++) s += qn_pf[w][t];
        g_qnsum_p[(nh*16 + tile)*64 + t] = s;
    } else if (t < 128) {
        int c = t - 64;
        float s = 0.f;
        #pragma unroll
        for (int w = 0; w < 8; w++) s += kn_pf[w][c];
        g_knsum_p[(nh*16 + tile)*64 + c] = s;
    }
}

// ---------------- K3: cr + tile max/expsum (sk only) + zero kv slice --------
__global__ void __launch_bounds__(256) k3_refine() {
    int nh = blockIdx.x, tile = blockIdx.y;    // 16 tiles x 256 rows
    int t = threadIdx.x;
    const size_t sbase = (size_t)nh * L_ * D_;
    int r0 = tile * 256;

    __shared__ float qnc[64];
    __shared__ float eps_c;
    __shared__ float mx_s[8], es_s[8];
    __shared__ float bmax_sh;

    if (t < 64)
        *(float4*)&g_kv[nh*4096 + tile*256 + t*4] = make_float4(0.f, 0.f, 0.f, 0.f);

    if (t >= 64 && t < 128) {
        int c = t - 64;
        float b = 0.f;
        #pragma unroll
        for (int cc = 0; cc < 16; cc++) b += g_qnsum_p[(nh*16 + cc)*64 + c];
        qnc[c] = b + EPSF;
    }
    __syncthreads();
    if (t == 0) {
        float b = 0.f;
        #pragma unroll
        for (int c = 0; c < 64; c++) b += qnc[c];
        eps_c = EPSF * b;
    }
    __syncthreads();

    int sub = t & 7, grp = t >> 3;
    float qnr[8];
    #pragma unroll
    for (int j = 0; j < 8; j++) qnr[j] = qnc[sub*8 + j];
    float epc = eps_c;

    const uint4* pk = (const uint4*)(g_sk + sbase);
    uint4 rk[8];
    #pragma unroll
    for (int i = 0; i < 8; i++) rk[i] = pk[(r0 + i*32 + grp)*8 + sub];

    float mx = 0.f;     // cr strictly positive
    float dcv[8];
    #pragma unroll
    for (int i = 0; i < 8; i++) {
        int r = r0 + i*32 + grp;
        unsigned wk[4] = {rk[i].x, rk[i].y, rk[i].z, rk[i].w};
        float dc = 0.f;
        #pragma unroll
        for (int j = 0; j < 4; j++) {
            float2 b = h22f2(wk[j]);
            dc += b.x*qnr[2*j] + b.y*qnr[2*j+1];
        }
        #pragma unroll
        for (int o = 1; o < 8; o <<= 1)
            dc += __shfl_xor_sync(0xffffffffu, dc, o);
        dc += epc;
        dcv[i] = dc;
        if (sub == 0) g_cr[nh*L_ + r] = dc;
        mx = fmaxf(mx, dc);
    }
    #pragma unroll
    for (int o = 16; o; o >>= 1) mx = fmaxf(mx, __shfl_xor_sync(0xffffffffu, mx, o));
    if ((t & 31) == 0) mx_s[t >> 5] = mx;
    __syncthreads();
    if (t == 0) {
        float m = mx_s[0];
        #pragma unroll
        for (int i = 1; i < 8; i++) m = fmaxf(m, mx_s[i]);
        bmax_sh = m;
        g_crmax_p[nh*16 + tile] = m;
    }
    __syncthreads();
    {
        float bmax = bmax_sh;
        float es = 0.f;
        if (sub == 0) {
            #pragma unroll
            for (int j = 0; j < 8; j++) es += __expf(dcv[j] - bmax);
        }
        #pragma unroll
        for (int o = 16; o; o >>= 1) es += __shfl_xor_sync(0xffffffffu, es, o);
        if ((t & 31) == 0) es_s[t >> 5] = es;
        __syncthreads();
        if (t == 0) {
            float s = 0.f;
            #pragma unroll
            for (int i = 0; i < 8; i++) s += es_s[i];
            g_expsum_p[nh*16 + tile] = s;
        }
    }
}

// ---------------- K5: kv += (w*sk)^T @ V, HMMA + v2 reductions --------------
__global__ void __launch_bounds__(256, 4) k5_kv(const float* __restrict__ V) {
    int nh = blockIdx.x, tile = blockIdx.y;    // 32 tiles x 128 rows
    int t = threadIdx.x;
    const int base = head_base(nh);
    const size_t sbase = (size_t)nh * L_ * D_;
    int s0g = tile * 128;

    __shared__ __align__(16) __half ksh[128*72];   // w*sk, s-major, pitch 72
    __shared__ __align__(16) __half vsh[128*72];   // V fp16 (unweighted), pitch 72
    __shared__ float wsh[128];

    // ---- front-issue ALL independent loads ----
    const uint4* skp = (const uint4*)(g_sk + sbase + (size_t)s0g * D_);
    uint4 skreg[4];
    #pragma unroll
    for (int p = 0; p < 4; p++) skreg[p] = skp[t + p*256];

    int l = t & 31;
    float crv = 0.f, pm = -1e30f, pe = 0.f;
    if (t < 128) {
        crv = g_cr[nh*L_ + s0g + t];
        if (l < 16) {
            pm = g_crmax_p[nh*16 + l];
            pe = g_expsum_p[nh*16 + l];
        }
    }

    // V fill — weight-independent, streams concurrently with the combine
    {
        int vrow = t >> 4, c4 = t & 15;
        #pragma unroll
        for (int p = 0; p < 8; p++) {
            int row = vrow + p*16;
            float4 f = ldg_cs_f4(V + base + (s0g + row)*RS + c4*4);
            __half2 h0 = __floats2half2_rn(f.x, f.y);
            __half2 h1 = __floats2half2_rn(f.z, f.w);
            uint2 u;
            u.x = *reinterpret_cast<unsigned*>(&h0);
            u.y = *reinterpret_cast<unsigned*>(&h1);
            *(uint2*)&vsh[row*72 + c4*4] = u;
        }
    }

    // per-warp redundant combine (warps 0-3), then weights
    if (t < 128) {
        float m = (l < 16) ? pm : -1e30f;
        #pragma unroll
        for (int o = 16; o; o >>= 1) m = fmaxf(m, __shfl_xor_sync(0xffffffffu, m, o));
        float e = (l < 16) ? __expf(pm - m) * pe : 0.f;
        #pragma unroll
        for (int o = 16; o; o >>= 1) e += __shfl_xor_sync(0xffffffffu, e, o);
        float scale = (float)L_ / e;
        wsh[t] = __expf(crv - m) * scale;
    }
    __syncthreads();

    // sk multiply by w (fp16) and store — short post-sync path
    #pragma unroll
    for (int p = 0; p < 4; p++) {
        int i = t + p*256;
        int row = i >> 3, j = i & 7;
        __half2 wv = __float2half2_rn(wsh[row]);
        uint4 u = skreg[p];
        __half2* h = (__half2*)&u;
        h[0] = __hmul2(h[0], wv); h[1] = __hmul2(h[1], wv);
        h[2] = __hmul2(h[2], wv); h[3] = __hmul2(h[3], wv);
        *(uint4*)&ksh[row*72 + j*8] = u;
    }
    __syncthreads();

    int w = t >> 5;
    int mt = w & 3, nhf = w >> 2;
    int m0 = mt * 16;
    int grow = l >> 2, kc = l & 3;
    float c[4][4] = {};

    int arow = (l & 7) + ((l >> 4) & 1) * 8;
    int acol = m0 + ((l >> 3) & 1) * 8;
    int brow = (l & 7) + ((l >> 3) & 1) * 8;
    int bcol = nhf*32 + (l >> 4) * 8;

    #pragma unroll
    for (int kt = 0; kt < 8; kt++) {
        unsigned a0, a1, a2, a3;
        ldsm_x4_t(a0, a1, a2, a3, smem_u32(&ksh[(kt*16 + arow)*72 + acol]));
        unsigned b0, b1, b2, b3, b4, b5, b6, b7;
        ldsm_x4_t(b0, b1, b2, b3, smem_u32(&vsh[(kt*16 + brow)*72 + bcol]));
        ldsm_x4_t(b4, b5, b6, b7, smem_u32(&vsh[(kt*16 + brow)*72 + bcol + 16]));
        mma16816(c[0][0], c[0][1], c[0][2], c[0][3], a0, a1, a2, a3, b0, b1);
        mma16816(c[1][0], c[1][1], c[1][2], c[1][3], a0, a1, a2, a3, b2, b3);
        mma16816(c[2][0], c[2][1], c[2][2], c[2][3], a0, a1, a2, a3, b4, b5);
        mma16816(c[3][0], c[3][1], c[3][2], c[3][3], a0, a1, a2, a3, b6, b7);
    }
    int drow = m0 + grow;
    #pragma unroll
    for (int nt = 0; nt < 4; nt++) {
        int e = nhf*32 + nt*8 + kc*2;
        float* dst = &g_kv[nh*4096 + drow*64 + e];
        red_add_v2(dst,       c[nt][0], c[nt][1]);
        red_add_v2(dst + 512, c[nt][2], c[nt][3]);   // row + 8
    }
}

// ---------------- K6: out = (sq @ kv) * rowfac, HMMA + ldmatrix feeds -------
__global__ void __launch_bounds__(256) k6_out(float* __restrict__ O) {
    int nh = blockIdx.x, tile = blockIdx.y;    // 32 tiles x 128 rows
    int t = threadIdx.x;
    const int base = head_base(nh);
    const size_t sbase = (size_t)nh * L_ * D_;
    int r0g = tile * 128;

    __shared__ __align__(16) __half qsh[128*72];   // sq rows, pitch 72
    __shared__ __align__(16) __half kvsh[64*72];   // kv fp16, d-major, pitch 72
    __shared__ float rf[128];
    __shared__ float knc_s[64];

    float nrow_reg = 0.f;
    if (t < 128) nrow_reg = g_nrow[nh*L_ + r0g + t];
    if (t < 64) {
        float a = 0.f;
        #pragma unroll
        for (int cc = 0; cc < 16; cc++) a += g_knsum_p[(nh*16 + cc)*64 + t];
        knc_s[t] = a + EPSF;
    }
    // qsh fill (plain loads — overlap via scoreboard)
    {
        const uint4* p = (const uint4*)(g_sq + sbase + (size_t)r0g * D_);
        #pragma unroll
        for (int pass = 0; pass < 4; pass++) {
            int i = t + pass*256;
            uint4 u = p[i];
            int row = i >> 3, j = i & 7;
            *(uint4*)&qsh[row*72 + j*8] = u;
        }
    }
    // kvsh fill: 64 rows x 64 floats -> fp16
    {
        #pragma unroll
        for (int p = 0; p < 4; p++) {
            int i = t + p*256;
            int row = i >> 4, c4 = i & 15;
            float4 f = *(const float4*)&g_kv[nh*4096 + row*64 + c4*4];
            __half2 h0 = __floats2half2_rn(f.x, f.y);
            __half2 h1 = __floats2half2_rn(f.z, f.w);
            uint2 u;
            u.x = *reinterpret_cast<unsigned*>(&h0);
            u.y = *reinterpret_cast<unsigned*>(&h1);
            *(uint2*)&kvsh[row*72 + c4*4] = u;
        }
    }
    __syncthreads();

    // rowfac from staged sq: rf = nrow * sigmoid(sum(sq*knc) + eps*sum(knc))
    if (t < 128) {
        const unsigned* row = (const unsigned*)&qsh[t*72];
        float d = 0.f, se = 0.f;
        #pragma unroll
        for (int j = 0; j < 32; j++) {
            float2 f = h22f2(row[j]);
            float c0 = knc_s[2*j], c1 = knc_s[2*j+1];
            d += f.x*c0 + f.y*c1;
            se += c0 + c1;
        }
        rf[t] = nrow_reg * sigmoidf(fmaf(EPSF, se, d));
    }
    __syncthreads();

    int w = t >> 5, l = t & 31;
    int rb = w * 16;
    int grow = l >> 2, kc = l & 3;
    float c[8][4] = {};

    int arow = rb + (l & 7) + ((l >> 3) & 1) * 8;
    int acol = (l >> 4) * 8;
    int brow = (l & 7) + ((l >> 3) & 1) * 8;
    int bcol = (l >> 4) * 8;

    #pragma unroll
    for (int kt = 0; kt < 4; kt++) {
        unsigned a0, a1, a2, a3;
        ldsm_x4(a0, a1, a2, a3, smem_u32(&qsh[arow*72 + kt*16 + acol]));
        #pragma unroll
        for (int nb = 0; nb < 4; nb++) {
            unsigned b0, b1, b2, b3;
            ldsm_x4_t(b0, b1, b2, b3,
                      smem_u32(&kvsh[(kt*16 + brow)*72 + nb*16 + bcol]));
            mma16816(c[nb*2][0],   c[nb*2][1],   c[nb*2][2],   c[nb*2][3],
                     a0, a1, a2, a3, b0, b1);
            mma16816(c[nb*2+1][0], c[nb*2+1][1], c[nb*2+1][2], c[nb*2+1][3],
                     a0, a1, a2, a3, b2, b3);
        }
    }
    int rA = r0g + rb + grow;
    float f0 = rf[rb + grow], f1 = rf[rb + grow + 8];
    #pragma unroll
    for (int nt = 0; nt < 8; nt++) {
        int e = nt*8 + kc*2;
        float2 o0; o0.x = c[nt][0] * f0; o0.y = c[nt][1] * f0;
        float2 o1; o1.x = c[nt][2] * f1; o1.y = c[nt][3] * f1;
        stg_cs_f2(O + base + rA*RS + e,     o0);
        stg_cs_f2(O + base + (rA+8)*RS + e, o1);
    }
}

// ---------------- launch ----------------------------------------------------
extern "C" void kernel_launch(void* const* d_in, const int* in_sizes, int n_in,
                              void* d_out, int out_size) {
    const float* Q = (const float*)d_in[0];
    const float* K = (const float*)d_in[1];
    const float* V = (const float*)d_in[2];
    float* O = (float*)d_out;

    k1_sums   <<<dim3(NH, 16), 256>>>(Q, K);
    k2_norm   <<<dim3(NH, 16), 256>>>();
    k3_refine <<<dim3(NH, 16), 256>>>();
    k5_kv     <<<dim3(NH, 32), 256>>>(V);
    k6_out    <<<dim3(NH, 32), 256>>>(O);
}